// round 8
// baseline (speedup 1.0000x reference)
#include <cuda_runtime.h>
#include <cstdint>

#define T_DIM  1024
#define KSZ    64
#define NSZ    64
#define CHUNK  64       // batch rows per pipeline stage
#define NCHUNK 8        // 512 / 64
#define NBUF   3
#define STR    68       // padded smem row stride (words) -> conflict-free frag LDS

__device__ __forceinline__ uint32_t f2tf32(float f) {
    uint32_t r; asm("cvt.rna.tf32.f32 %0, %1;" : "=r"(r) : "f"(f)); return r;
}
__device__ __forceinline__ uint32_t smem_u32(const void* p) {
    uint32_t a;
    asm("{ .reg .u64 t; cvta.to.shared.u64 t, %1; cvt.u32.u64 %0, t; }" : "=r"(a) : "l"(p));
    return a;
}
__device__ __forceinline__ void cp_async16(uint32_t dst, const void* src) {
    asm volatile("cp.async.cg.shared.global [%0], [%1], 16;" :: "r"(dst), "l"(src));
}

__global__ __launch_bounds__(256, 3)
void parallel_linear_pipe3(const float* __restrict__ x,
                           const float* __restrict__ W,
                           const float* __restrict__ bias,
                           float* __restrict__ out)
{
    extern __shared__ float smem[];
    float*    sAbase = smem;                                   // NBUF x CHUNK x STR
    uint32_t* sW = reinterpret_cast<uint32_t*>(smem + NBUF * CHUNK * STR);
    float*    sB = reinterpret_cast<float*>(sW + NSZ * STR);

    const int t    = blockIdx.x;
    const int tid  = threadIdx.x;
    const int warp = tid >> 5;
    const int lane = tid & 31;
    const int g    = lane >> 2;        // 0..7
    const int tg   = lane & 3;         // 0..3
    const int nquad = warp & 3;        // 16-col block
    const int mhalf = warp >> 2;       // 32-row block within chunk

    const size_t rowstride = (size_t)T_DIM * KSZ;

    // ---- prologue: issue cp.async for chunks 0 and 1 ----
    #pragma unroll
    for (int cc = 0; cc < 2; cc++) {
        float* dst = sAbase + cc * (CHUNK * STR);
        #pragma unroll
        for (int i = 0; i < 4; i++) {
            int idx = tid + i * 256;       // float4 id 0..1023
            int r   = idx >> 4;            // row 0..63
            int c4  = idx & 15;
            const float* src = x + ((size_t)(cc * CHUNK + r) * T_DIM + t) * KSZ + c4 * 4;
            cp_async16(smem_u32(&dst[r * STR + c4 * 4]), src);
        }
        asm volatile("cp.async.commit_group;");
    }

    // ---- stage W_t [64,64] -> tf32 bits in smem (overlaps with async X loads) ----
    {
        const float4* Wg = reinterpret_cast<const float4*>(W + (size_t)t * (NSZ * KSZ));
        #pragma unroll
        for (int i = 0; i < 4; i++) {
            int idx = tid + i * 256;
            int n   = idx >> 4;
            int c4  = idx & 15;
            float4 v = Wg[n * 16 + c4];
            uint4 u = make_uint4(f2tf32(v.x), f2tf32(v.y), f2tf32(v.z), f2tf32(v.w));
            *reinterpret_cast<uint4*>(&sW[n * STR + c4 * 4]) = u;
        }
    }
    if (tid < NSZ) sB[tid] = bias[t * NSZ + tid];
    __syncthreads();

    // ---- W fragments once into registers: 2 n-tiles x 8 ks x 2 = 32 regs ----
    uint32_t wf0[2][8], wf1[2][8];
    #pragma unroll
    for (int nt = 0; nt < 2; nt++) {
        const int ncol = nquad * 16 + nt * 8 + g;
        #pragma unroll
        for (int ks = 0; ks < 8; ks++) {
            wf0[nt][ks] = sW[ncol * STR + ks * 8 + tg];
            wf1[nt][ks] = sW[ncol * STR + ks * 8 + tg + 4];
        }
    }
    float bb0[2], bb1[2];
    #pragma unroll
    for (int nt = 0; nt < 2; nt++) {
        bb0[nt] = sB[nquad * 16 + nt * 8 + 2 * tg];
        bb1[nt] = sB[nquad * 16 + nt * 8 + 2 * tg + 1];
    }

    // ---- pipelined mainloop over 8 chunks, 3 buffers ----
    #pragma unroll 1
    for (int c = 0; c < NCHUNK; c++) {
        if (c < NCHUNK - 1) asm volatile("cp.async.wait_group 1;");
        else                asm volatile("cp.async.wait_group 0;");
        __syncthreads();   // chunk c visible to all; all warps done with chunk c-1

        // issue chunk c+2 into buffer (c+2)%3 (== buffer of chunk c-1, now free)
        if (c + 2 < NCHUNK) {
            float* dst = sAbase + ((c + 2) % NBUF) * (CHUNK * STR);
            const float* srcb = x + ((size_t)((c + 2) * CHUNK) * T_DIM + t) * KSZ;
            #pragma unroll
            for (int i = 0; i < 4; i++) {
                int idx = tid + i * 256;
                int r   = idx >> 4;
                int c4  = idx & 15;
                cp_async16(smem_u32(&dst[r * STR + c4 * 4]),
                           srcb + (size_t)r * rowstride + c4 * 4);
            }
            asm volatile("cp.async.commit_group;");
        }

        const float* aBuf = sAbase + (c % NBUF) * (CHUNK * STR);

        #pragma unroll
        for (int mt = 0; mt < 2; mt++) {
            const int rb = mhalf * 32 + mt * 16;
            float acc[2][4];
            #pragma unroll
            for (int nt = 0; nt < 2; nt++)
                #pragma unroll
                for (int j = 0; j < 4; j++) acc[nt][j] = 0.f;

            #pragma unroll
            for (int ks = 0; ks < 8; ks++) {
                const int k0 = ks * 8;
                uint32_t a0 = f2tf32(aBuf[(rb + g)     * STR + k0 + tg]);
                uint32_t a1 = f2tf32(aBuf[(rb + 8 + g) * STR + k0 + tg]);
                uint32_t a2 = f2tf32(aBuf[(rb + g)     * STR + k0 + tg + 4]);
                uint32_t a3 = f2tf32(aBuf[(rb + 8 + g) * STR + k0 + tg + 4]);
                #pragma unroll
                for (int nt = 0; nt < 2; nt++) {
                    asm volatile(
                        "mma.sync.aligned.m16n8k8.row.col.f32.tf32.tf32.f32 "
                        "{%0,%1,%2,%3}, {%4,%5,%6,%7}, {%8,%9}, {%0,%1,%2,%3};"
                        : "+f"(acc[nt][0]), "+f"(acc[nt][1]),
                          "+f"(acc[nt][2]), "+f"(acc[nt][3])
                        : "r"(a0), "r"(a1), "r"(a2), "r"(a3),
                          "r"(wf0[nt][ks]), "r"(wf1[nt][ks]));
                }
            }

            const int grow = c * CHUNK + rb + g;
            #pragma unroll
            for (int nt = 0; nt < 2; nt++) {
                const int col = nquad * 16 + nt * 8 + 2 * tg;
                size_t base = ((size_t)grow * T_DIM + t) * KSZ + col;
                *reinterpret_cast<float2*>(out + base) =
                    make_float2(acc[nt][0] + bb0[nt], acc[nt][1] + bb1[nt]);
                *reinterpret_cast<float2*>(out + base + 8 * rowstride) =
                    make_float2(acc[nt][2] + bb0[nt], acc[nt][3] + bb1[nt]);
            }
        }
    }
}

extern "C" void kernel_launch(void* const* d_in, const int* in_sizes, int n_in,
                              void* d_out, int out_size)
{
    const float* x = (const float*)d_in[0];
    const float* W = (const float*)d_in[1];
    const float* b = (const float*)d_in[2];
    float* out     = (float*)d_out;

    const int smem_bytes =
        (NBUF * CHUNK * STR + NSZ * STR + NSZ) * (int)sizeof(float);  // 70 KB

    cudaFuncSetAttribute(parallel_linear_pipe3,
                         cudaFuncAttributeMaxDynamicSharedMemorySize, smem_bytes);

    parallel_linear_pipe3<<<T_DIM, 256, smem_bytes>>>(x, W, b, out);
}

// round 9
// speedup vs baseline: 1.1399x; 1.1399x over previous
#include <cuda_runtime.h>
#include <cstdint>

#define T_DIM  1024
#define KSZ    64
#define NSZ    64
#define CHUNK  128      // batch rows per pipeline stage
#define NCHUNK 4        // 512 / 128
#define NBUF   3
#define AWORDS (CHUNK * KSZ)   // words per A chunk (swizzled, no padding)

// XOR-swizzled word offset inside an A chunk: conflict-free for both the
// cp.async float4 stores and the (g,tg) fragment loads.
__device__ __forceinline__ int swz(int row, int col) {
    return row * KSZ + (col ^ ((row & 7) << 2));
}

__device__ __forceinline__ uint32_t f2tf32(float f) {
    uint32_t r; asm("cvt.rna.tf32.f32 %0, %1;" : "=r"(r) : "f"(f)); return r;
}
__device__ __forceinline__ uint32_t smem_u32(const void* p) {
    uint32_t a;
    asm("{ .reg .u64 t; cvta.to.shared.u64 t, %1; cvt.u32.u64 %0, t; }" : "=r"(a) : "l"(p));
    return a;
}
__device__ __forceinline__ void cp_async16(uint32_t dst, const void* src) {
    asm volatile("cp.async.cg.shared.global [%0], [%1], 16;" :: "r"(dst), "l"(src));
}

__global__ __launch_bounds__(256, 2)
void parallel_linear_pipe(const float* __restrict__ x,
                          const float* __restrict__ W,
                          const float* __restrict__ bias,
                          float* __restrict__ out)
{
    extern __shared__ float smem[];
    float*    sAbase = smem;                                     // NBUF x AWORDS
    uint32_t* sW = reinterpret_cast<uint32_t*>(smem + NBUF * AWORDS); // 64x64 tf32
    float*    sB = reinterpret_cast<float*>(sW + NSZ * KSZ);

    const int t    = blockIdx.x;
    const int tid  = threadIdx.x;
    const int warp = tid >> 5;
    const int lane = tid & 31;
    const int g    = lane >> 2;          // 0..7
    const int tg   = lane & 3;           // 0..3
    const int nhalf  = warp & 1;         // 32-col half
    const int mgroup = warp >> 1;        // 32-row group within chunk

    const size_t rowstride = (size_t)T_DIM * KSZ;

    // ---- prologue: issue cp.async for chunks 0 and 1 ----
    #pragma unroll
    for (int cc = 0; cc < 2; cc++) {
        float* dst = sAbase + cc * AWORDS;
        #pragma unroll
        for (int i = 0; i < 8; i++) {
            int idx = tid + i * 256;         // float4 id 0..2047
            int r   = idx >> 4;              // row 0..127
            int c4  = idx & 15;
            const float* src = x + ((size_t)(cc * CHUNK + r) * T_DIM + t) * KSZ + c4 * 4;
            cp_async16(smem_u32(&dst[swz(r, c4 * 4)]), src);
        }
        asm volatile("cp.async.commit_group;");
    }

    // ---- stage W_t [64,64] -> tf32 bits, unpadded (frag load is one-time) ----
    {
        const float4* Wg = reinterpret_cast<const float4*>(W + (size_t)t * (NSZ * KSZ));
        #pragma unroll
        for (int i = 0; i < 4; i++) {
            int idx = tid + i * 256;
            int n   = idx >> 4;
            int c4  = idx & 15;
            float4 v = Wg[n * 16 + c4];
            uint4 u = make_uint4(f2tf32(v.x), f2tf32(v.y), f2tf32(v.z), f2tf32(v.w));
            *reinterpret_cast<uint4*>(&sW[n * KSZ + c4 * 4]) = u;
        }
    }
    if (tid < NSZ) sB[tid] = bias[t * NSZ + tid];
    __syncthreads();

    // ---- W fragments ONCE into registers: 4 n-tiles x 8 ks x 2 = 64 regs ----
    uint32_t wf0[4][8], wf1[4][8];
    #pragma unroll
    for (int nt = 0; nt < 4; nt++) {
        const int ncol = nhalf * 32 + nt * 8 + g;
        #pragma unroll
        for (int ks = 0; ks < 8; ks++) {
            wf0[nt][ks] = sW[ncol * KSZ + ks * 8 + tg];
            wf1[nt][ks] = sW[ncol * KSZ + ks * 8 + tg + 4];
        }
    }
    float bb0[4], bb1[4];
    #pragma unroll
    for (int nt = 0; nt < 4; nt++) {
        bb0[nt] = sB[nhalf * 32 + nt * 8 + 2 * tg];
        bb1[nt] = sB[nhalf * 32 + nt * 8 + 2 * tg + 1];
    }

    // ---- pipelined mainloop: 4 chunks, 3 buffers, loads issued BEFORE compute ----
    #pragma unroll 1
    for (int c = 0; c < NCHUNK; c++) {
        if (c < NCHUNK - 1) asm volatile("cp.async.wait_group 1;");
        else                asm volatile("cp.async.wait_group 0;");
        __syncthreads();   // chunk c visible; all warps done with chunk c-1's buffer

        if (c + 2 < NCHUNK) {   // refill buffer of chunk c-1 with chunk c+2
            float* dst = sAbase + ((c + 2) % NBUF) * AWORDS;
            const float* srcb = x + ((size_t)((c + 2) * CHUNK) * T_DIM + t) * KSZ;
            #pragma unroll
            for (int i = 0; i < 8; i++) {
                int idx = tid + i * 256;
                int r   = idx >> 4;
                int c4  = idx & 15;
                cp_async16(smem_u32(&dst[swz(r, c4 * 4)]),
                           srcb + (size_t)r * rowstride + c4 * 4);
            }
            asm volatile("cp.async.commit_group;");
        }

        const float* aBuf = sAbase + (c % NBUF) * AWORDS;

        #pragma unroll
        for (int mt = 0; mt < 2; mt++) {
            const int rb = mgroup * 32 + mt * 16;
            float acc[4][4];
            #pragma unroll
            for (int nt = 0; nt < 4; nt++)
                #pragma unroll
                for (int j = 0; j < 4; j++) acc[nt][j] = 0.f;

            #pragma unroll
            for (int ks = 0; ks < 8; ks++) {
                const int k0 = ks * 8;
                uint32_t a0 = f2tf32(aBuf[swz(rb + g,     k0 + tg)]);
                uint32_t a1 = f2tf32(aBuf[swz(rb + 8 + g, k0 + tg)]);
                uint32_t a2 = f2tf32(aBuf[swz(rb + g,     k0 + tg + 4)]);
                uint32_t a3 = f2tf32(aBuf[swz(rb + 8 + g, k0 + tg + 4)]);
                #pragma unroll
                for (int nt = 0; nt < 4; nt++) {
                    asm volatile(
                        "mma.sync.aligned.m16n8k8.row.col.f32.tf32.tf32.f32 "
                        "{%0,%1,%2,%3}, {%4,%5,%6,%7}, {%8,%9}, {%0,%1,%2,%3};"
                        : "+f"(acc[nt][0]), "+f"(acc[nt][1]),
                          "+f"(acc[nt][2]), "+f"(acc[nt][3])
                        : "r"(a0), "r"(a1), "r"(a2), "r"(a3),
                          "r"(wf0[nt][ks]), "r"(wf1[nt][ks]));
                }
            }

            const int grow = c * CHUNK + rb + g;
            #pragma unroll
            for (int nt = 0; nt < 4; nt++) {
                const int col = nhalf * 32 + nt * 8 + 2 * tg;
                size_t base = ((size_t)grow * T_DIM + t) * KSZ + col;
                *reinterpret_cast<float2*>(out + base) =
                    make_float2(acc[nt][0] + bb0[nt], acc[nt][1] + bb1[nt]);
                *reinterpret_cast<float2*>(out + base + 8 * rowstride) =
                    make_float2(acc[nt][2] + bb0[nt], acc[nt][3] + bb1[nt]);
            }
        }
    }
}

extern "C" void kernel_launch(void* const* d_in, const int* in_sizes, int n_in,
                              void* d_out, int out_size)
{
    const float* x = (const float*)d_in[0];
    const float* W = (const float*)d_in[1];
    const float* b = (const float*)d_in[2];
    float* out     = (float*)d_out;

    const int smem_bytes =
        (NBUF * AWORDS + NSZ * KSZ + NSZ) * (int)sizeof(float);  // 114944 B

    cudaFuncSetAttribute(parallel_linear_pipe,
                         cudaFuncAttributeMaxDynamicSharedMemorySize, smem_bytes);

    parallel_linear_pipe<<<T_DIM, 256, smem_bytes>>>(x, W, b, out);
}

// round 11
// speedup vs baseline: 1.4945x; 1.3111x over previous
#include <cuda_runtime.h>
#include <cstdint>

#define T_DIM  1024
#define KSZ    64
#define NSZ    64
#define CHUNK  64       // batch rows per pipeline stage
#define NCHUNK 8        // 512 / 64
#define NBUF   4
#define STR    68       // padded smem row stride (words): frag LDS bank = 4g+tg, conflict-free
#define ABUF   (CHUNK * STR)

__device__ __forceinline__ uint32_t f2tf32(float f) {
    uint32_t r; asm("cvt.rna.tf32.f32 %0, %1;" : "=r"(r) : "f"(f)); return r;
}
__device__ __forceinline__ uint32_t smem_u32(const void* p) {
    uint32_t a;
    asm("{ .reg .u64 t; cvta.to.shared.u64 t, %1; cvt.u32.u64 %0, t; }" : "=r"(a) : "l"(p));
    return a;
}
__device__ __forceinline__ void cp_async16(uint32_t dst, const void* src) {
    asm volatile("cp.async.cg.shared.global [%0], [%1], 16;" :: "r"(dst), "l"(src));
}

// issue one 64-row chunk (64x64 fp32 = 16 KB) as 1024 cp.async float4s + commit
__device__ __forceinline__ void issue_chunk(float* dst, const float* __restrict__ x,
                                            int t, int rowBase, int tid)
{
    #pragma unroll
    for (int i = 0; i < 4; i++) {
        int idx = tid + i * 256;          // float4 id 0..1023
        int r   = idx >> 4;               // row 0..63
        int c4  = idx & 15;
        const float* src = x + ((size_t)(rowBase + r) * T_DIM + t) * KSZ + c4 * 4;
        cp_async16(smem_u32(&dst[r * STR + c4 * 4]), src);
    }
    asm volatile("cp.async.commit_group;");
}

__global__ __launch_bounds__(256, 2)
void parallel_linear_deep(const float* __restrict__ x,
                          const float* __restrict__ W,
                          const float* __restrict__ bias,
                          float* __restrict__ out)
{
    extern __shared__ float smem[];
    float*    sAbase = smem;                                    // NBUF x ABUF
    uint32_t* sW = reinterpret_cast<uint32_t*>(smem + NBUF * ABUF); // 64 x STR tf32
    float*    sB = reinterpret_cast<float*>(sW + NSZ * STR);

    const int t    = blockIdx.x;
    const int tid  = threadIdx.x;
    const int warp = tid >> 5;
    const int lane = tid & 31;
    const int g    = lane >> 2;        // 0..7
    const int tg   = lane & 3;         // 0..3
    const int nhalf = warp & 1;        // 32-col half
    const int rb    = (warp >> 1) * 16; // 16-row block within chunk (warp tile 16x32)

    const size_t rowstride = (size_t)T_DIM * KSZ;

    // ---- prologue: chunks 0,1,2 in flight ----
    issue_chunk(sAbase + 0 * ABUF, x, t, 0 * CHUNK, tid);
    issue_chunk(sAbase + 1 * ABUF, x, t, 1 * CHUNK, tid);
    issue_chunk(sAbase + 2 * ABUF, x, t, 2 * CHUNK, tid);

    // ---- stage W_t [64,64] -> tf32 bits (overlaps the async X loads) ----
    {
        const float4* Wg = reinterpret_cast<const float4*>(W + (size_t)t * (NSZ * KSZ));
        #pragma unroll
        for (int i = 0; i < 4; i++) {
            int idx = tid + i * 256;
            int n   = idx >> 4;
            int c4  = idx & 15;
            float4 v = Wg[n * 16 + c4];
            uint4 u = make_uint4(f2tf32(v.x), f2tf32(v.y), f2tf32(v.z), f2tf32(v.w));
            *reinterpret_cast<uint4*>(&sW[n * STR + c4 * 4]) = u;
        }
    }
    if (tid < NSZ) sB[tid] = bias[t * NSZ + tid];
    __syncthreads();

    // ---- W fragments ONCE into registers: 4 n-tiles x 8 ks x 2 = 64 regs ----
    uint32_t wf0[4][8], wf1[4][8];
    #pragma unroll
    for (int nt = 0; nt < 4; nt++) {
        const int ncol = nhalf * 32 + nt * 8 + g;
        #pragma unroll
        for (int ks = 0; ks < 8; ks++) {
            wf0[nt][ks] = sW[ncol * STR + ks * 8 + tg];
            wf1[nt][ks] = sW[ncol * STR + ks * 8 + tg + 4];
        }
    }
    float bb0[4], bb1[4];
    #pragma unroll
    for (int nt = 0; nt < 4; nt++) {
        bb0[nt] = sB[nhalf * 32 + nt * 8 + 2 * tg];
        bb1[nt] = sB[nhalf * 32 + nt * 8 + 2 * tg + 1];
    }

    // ---- fully unrolled 8-chunk pipeline, 4 buffers, refill BEFORE compute ----
    #pragma unroll
    for (int c = 0; c < NCHUNK; c++) {
        // wait until chunk c is resident: pending groups <= min(2, NCHUNK-1-c)
        if      (c <= NCHUNK - 4) asm volatile("cp.async.wait_group 2;");
        else if (c == NCHUNK - 3) asm volatile("cp.async.wait_group 1;");
        else                      asm volatile("cp.async.wait_group 0;");
        __syncthreads();   // chunk c visible; buffer of chunk c-1 free for all warps

        if (c + 3 < NCHUNK)   // refill freed buffer with chunk c+3 (compile-time ptr)
            issue_chunk(sAbase + ((c + 3) & (NBUF - 1)) * ABUF, x, t, (c + 3) * CHUNK, tid);

        const float* aBuf = sAbase + (c & (NBUF - 1)) * ABUF;

        float acc[4][4];
        #pragma unroll
        for (int nt = 0; nt < 4; nt++)
            #pragma unroll
            for (int j = 0; j < 4; j++) acc[nt][j] = 0.f;

        #pragma unroll
        for (int ks = 0; ks < 8; ks++) {
            const int k0 = ks * 8;
            uint32_t a0 = f2tf32(aBuf[(rb + g)     * STR + k0 + tg]);
            uint32_t a1 = f2tf32(aBuf[(rb + 8 + g) * STR + k0 + tg]);
            uint32_t a2 = f2tf32(aBuf[(rb + g)     * STR + k0 + tg + 4]);
            uint32_t a3 = f2tf32(aBuf[(rb + 8 + g) * STR + k0 + tg + 4]);
            #pragma unroll
            for (int nt = 0; nt < 4; nt++) {
                asm volatile(
                    "mma.sync.aligned.m16n8k8.row.col.f32.tf32.tf32.f32 "
                    "{%0,%1,%2,%3}, {%4,%5,%6,%7}, {%8,%9}, {%0,%1,%2,%3};"
                    : "+f"(acc[nt][0]), "+f"(acc[nt][1]),
                      "+f"(acc[nt][2]), "+f"(acc[nt][3])
                    : "r"(a0), "r"(a1), "r"(a2), "r"(a3),
                      "r"(wf0[nt][ks]), "r"(wf1[nt][ks]));
            }
        }

        // epilogue: +bias, float2 stores
        const int grow = c * CHUNK + rb + g;
        #pragma unroll
        for (int nt = 0; nt < 4; nt++) {
            const int col = nhalf * 32 + nt * 8 + 2 * tg;
            size_t base = ((size_t)grow * T_DIM + t) * KSZ + col;
            *reinterpret_cast<float2*>(out + base) =
                make_float2(acc[nt][0] + bb0[nt], acc[nt][1] + bb1[nt]);
            *reinterpret_cast<float2*>(out + base + 8 * rowstride) =
                make_float2(acc[nt][2] + bb0[nt], acc[nt][3] + bb1[nt]);
        }
    }
}

extern "C" void kernel_launch(void* const* d_in, const int* in_sizes, int n_in,
                              void* d_out, int out_size)
{
    const float* x = (const float*)d_in[0];
    const float* W = (const float*)d_in[1];
    const float* b = (const float*)d_in[2];
    float* out     = (float*)d_out;

    const int smem_bytes =
        (NBUF * ABUF + NSZ * STR + NSZ) * (int)sizeof(float);   // 87296 B

    cudaFuncSetAttribute(parallel_linear_deep,
                         cudaFuncAttributeMaxDynamicSharedMemorySize, smem_bytes);

    parallel_linear_deep<<<T_DIM, 256, smem_bytes>>>(x, W, b, out);
}